// round 7
// baseline (speedup 1.0000x reference)
#include <cuda_runtime.h>

// OpenLSTM: B=4096 sequences, T=1024, HID=16, PROJ=2.
// t < 256 teacher-forced; t >= 256 recurrent.
//
// R7: TPE=16 + EPT=2 (each thread: unit j of TWO elements) -> 4 elements/warp,
// 1024 warps. The two streams are fully independent, giving the recurrent
// phase ILP=2 to hide the ~170cyc serial chain that R5's teacher phase proved
// is the gap (teacher 210 cyc/step vs recurrent 375 at identical instr mix).
// Code staged batch-wise (gates both / TANHs both / c both / butterflies
// interleaved) exactly like the proven teacher batching.
// Chain trim: p = b*tanh(c), b = fma(wr,to,wr) precomputed off-chain.

#define T_TOTAL 1024
#define N_CTX   256
#define TPE     16
#define EPT     2
#define EPW     4     // elements per 32-thread warp/block
#define TU      2     // teacher time-unroll (x EPT=2 -> 4-way ILP)

__device__ __forceinline__ float tanh_fast(float x) {
    float y;
    asm("tanh.approx.f32 %0, %1;" : "=f"(y) : "f"(x));
    return y;
}

__global__ void __launch_bounds__(32)
open_lstm_kernel(const float* __restrict__ u,     // (B, T, 4)
                 const float* __restrict__ w_ih,  // (64, 2)
                 const float* __restrict__ w_hh,  // (64, 2)
                 const float* __restrict__ b_ih,  // (64)
                 const float* __restrict__ b_hh,  // (64)
                 const float* __restrict__ w_hr,  // (2, 16)
                 float* __restrict__ out)         // (B, T, 2)
{
    const int lane = threadIdx.x;
    const int j    = lane & (TPE - 1);            // hidden unit 0..15
    const int sg   = lane >> 4;                   // spatial group 0/1
    const int e0   = blockIdx.x * EPW + sg * EPT; // elements e0, e0+1

    // Weights for unit j (shared by both element streams).
    // sigma(x)=0.5*tanh(0.5x)+0.5 folded: i/f/o rows pre-scaled by 0.5;
    // o-path outer 0.5 folded into w_hr.
    float wi[4][2], wh[4][2], bb[4], wr0, wr1;
#pragma unroll
    for (int k = 0; k < 4; k++) {
        const int r = k * 16 + j;
        const float sc = (k == 2) ? 1.0f : 0.5f;
        wi[k][0] = w_ih[r * 2 + 0] * sc;
        wi[k][1] = w_ih[r * 2 + 1] * sc;
        wh[k][0] = w_hh[r * 2 + 0] * sc;
        wh[k][1] = w_hh[r * 2 + 1] * sc;
        bb[k]    = (b_ih[r] + b_hh[r]) * sc;
    }
    wr0 = w_hr[j]      * 0.5f;
    wr1 = w_hr[16 + j] * 0.5f;

    const float4* __restrict__ up[EPT];
    float2* __restrict__ op[EPT];
#pragma unroll
    for (int ee = 0; ee < EPT; ee++) {
        up[ee] = (const float4*)u + (size_t)(e0 + ee) * T_TOTAL;
        op[ee] = (float2*)out + (size_t)(e0 + ee) * T_TOTAL;
    }

    float c[EPT] = {0.0f, 0.0f};
    float h0[EPT] = {0.0f, 0.0f}, h1[EPT] = {0.0f, 0.0f};

    // ================= teacher-forced phase: TU=2 x EPT=2 = 4-way ILP =========
#pragma unroll 1
    for (int t = 0; t < N_CTX; t += TU) {
        float4 vv[EPT][TU];
#pragma unroll
        for (int ee = 0; ee < EPT; ee++)
#pragma unroll
            for (int s = 0; s < TU; s++) vv[ee][s] = up[ee][t + s];

        float gg[EPT][TU][4];
#pragma unroll
        for (int ee = 0; ee < EPT; ee++)
#pragma unroll
            for (int s = 0; s < TU; s++)
#pragma unroll
                for (int k = 0; k < 4; k++)
                    gg[ee][s][k] = fmaf(wi[k][0], vv[ee][s].x,
                                   fmaf(wi[k][1], vv[ee][s].y,
                                   fmaf(wh[k][0], vv[ee][s].z,
                                   fmaf(wh[k][1], vv[ee][s].w, bb[k]))));

        float ti[EPT][TU], tf[EPT][TU], tg[EPT][TU], to[EPT][TU];
#pragma unroll
        for (int ee = 0; ee < EPT; ee++)
#pragma unroll
            for (int s = 0; s < TU; s++) {
                ti[ee][s] = tanh_fast(gg[ee][s][0]);
                tf[ee][s] = tanh_fast(gg[ee][s][1]);
                tg[ee][s] = tanh_fast(gg[ee][s][2]);
                to[ee][s] = tanh_fast(gg[ee][s][3]);
            }

        float tc[EPT][TU];
#pragma unroll
        for (int ee = 0; ee < EPT; ee++)
#pragma unroll
            for (int s = 0; s < TU; s++) {
                float ca = fmaf(tf[ee][s], c[ee], c[ee]);       // 2*sig(f)*c
                float cb = fmaf(ti[ee][s], tg[ee][s], tg[ee][s]); // 2*sig(i)*tanh(g)
                c[ee] = fmaf(0.5f, ca, 0.5f * cb);
                tc[ee][s] = tanh_fast(c[ee]);
            }

        float p0[EPT][TU], p1[EPT][TU];
#pragma unroll
        for (int ee = 0; ee < EPT; ee++)
#pragma unroll
            for (int s = 0; s < TU; s++) {
                float b0 = fmaf(wr0, to[ee][s], wr0);  // wr0*(1+to)
                float b1 = fmaf(wr1, to[ee][s], wr1);
                p0[ee][s] = b0 * tc[ee][s];
                p1[ee][s] = b1 * tc[ee][s];
            }
#pragma unroll
        for (int k = 1; k < TPE; k <<= 1) {
#pragma unroll
            for (int ee = 0; ee < EPT; ee++)
#pragma unroll
                for (int s = 0; s < TU; s++) {
                    p0[ee][s] += __shfl_xor_sync(0xffffffffu, p0[ee][s], k, TPE);
                    p1[ee][s] += __shfl_xor_sync(0xffffffffu, p1[ee][s], k, TPE);
                }
        }
#pragma unroll
        for (int ee = 0; ee < EPT; ee++) {
            if (j == 0) {
#pragma unroll
                for (int s = 0; s < TU; s++)
                    op[ee][t + s] = make_float2(p0[ee][s], p1[ee][s]);
            }
            h0[ee] = p0[ee][TU - 1];
            h1[ee] = p1[ee][TU - 1];
        }
    }

    // ================= recurrent phase: EPT=2 dual-stream =====================
    float xp[EPT][4];
    float4 v[EPT];
#pragma unroll
    for (int ee = 0; ee < EPT; ee++) {
        v[ee] = up[ee][N_CTX];
#pragma unroll
        for (int k = 0; k < 4; k++)
            xp[ee][k] = fmaf(wi[k][0], v[ee].x, fmaf(wi[k][1], v[ee].y, bb[k]));
    }

#pragma unroll 1
    for (int t = N_CTX; t < T_TOTAL; t++) {
        const int tn = (t + 1 < T_TOTAL) ? (t + 1) : t;
        float4 vn[EPT];
#pragma unroll
        for (int ee = 0; ee < EPT; ee++) vn[ee] = up[ee][tn];

        // stage 1: gates (h-dependent part), both streams
        float gg[EPT][4];
#pragma unroll
        for (int ee = 0; ee < EPT; ee++)
#pragma unroll
            for (int k = 0; k < 4; k++)
                gg[ee][k] = fmaf(wh[k][0], h0[ee],
                            fmaf(wh[k][1], h1[ee], xp[ee][k]));

        // stage 2: 8 gate TANHs, all independent
        float ti[EPT], tf[EPT], tg[EPT], to[EPT];
#pragma unroll
        for (int ee = 0; ee < EPT; ee++) {
            ti[ee] = tanh_fast(gg[ee][0]);
            tf[ee] = tanh_fast(gg[ee][1]);
            tg[ee] = tanh_fast(gg[ee][2]);
            to[ee] = tanh_fast(gg[ee][3]);
        }

        // stage 3: c update + tanh(c) + off-chain b coefficients
        float tc[EPT], b0[EPT], b1[EPT];
#pragma unroll
        for (int ee = 0; ee < EPT; ee++) {
            float cb = fmaf(ti[ee], tg[ee], tg[ee]);
            float ca = fmaf(tf[ee], c[ee], c[ee]);
            c[ee] = fmaf(0.5f, ca, 0.5f * cb);
            tc[ee] = tanh_fast(c[ee]);
            b0[ee] = fmaf(wr0, to[ee], wr0);   // off critical chain
            b1[ee] = fmaf(wr1, to[ee], wr1);
        }

        // stage 4: projections
        float p0[EPT], p1[EPT];
#pragma unroll
        for (int ee = 0; ee < EPT; ee++) {
            p0[ee] = b0[ee] * tc[ee];
            p1[ee] = b1[ee] * tc[ee];
        }

        // stage 5: butterflies, rounds interleaved across streams
#pragma unroll
        for (int k = 1; k < TPE; k <<= 1) {
#pragma unroll
            for (int ee = 0; ee < EPT; ee++) {
                p0[ee] += __shfl_xor_sync(0xffffffffu, p0[ee], k, TPE);
                p1[ee] += __shfl_xor_sync(0xffffffffu, p1[ee], k, TPE);
            }
        }

        // stage 6: commit + next-step x-part (off-chain filler)
#pragma unroll
        for (int ee = 0; ee < EPT; ee++) {
            h0[ee] = p0[ee]; h1[ee] = p1[ee];
            if (j == 0) op[ee][t] = make_float2(p0[ee], p1[ee]);
#pragma unroll
            for (int k = 0; k < 4; k++)
                xp[ee][k] = fmaf(wi[k][0], vn[ee].x,
                            fmaf(wi[k][1], vn[ee].y, bb[k]));
            v[ee] = vn[ee];
        }
    }
}

extern "C" void kernel_launch(void* const* d_in, const int* in_sizes, int n_in,
                              void* d_out, int out_size)
{
    const float* u    = (const float*)d_in[0];
    const float* w_ih = (const float*)d_in[1];
    const float* w_hh = (const float*)d_in[2];
    const float* b_ih = (const float*)d_in[3];
    const float* b_hh = (const float*)d_in[4];
    const float* w_hr = (const float*)d_in[5];
    float* out = (float*)d_out;

    const int B = in_sizes[0] / (T_TOTAL * 4);   // 4096
    const int grid = B / EPW;                    // 1024 blocks x 32 threads

    open_lstm_kernel<<<grid, 32>>>(u, w_ih, w_hh, b_ih, b_hh, w_hr, out);
}